// round 7
// baseline (speedup 1.0000x reference)
#include <cuda_runtime.h>
#include <cstdint>
#include <math.h>

#define N_ROWS   100000
#define C_CLS    20
#define D_DIM    2001
#define D_PAD    2016          // W smem zero-padded so tail tiles contribute 0
#define NCHUNK   3
#define CHUNK    672           // D_PAD / 3
#define TILE     8             // cols per X tile
#define NTILES   (CHUNK / TILE)         // 84
#define ROWBLK   64            // rows per warp-task (2 per lane)
#define NRB      ((N_ROWS + ROWBLK - 1) / ROWBLK)   // 1563
#define NTASK    (NRB * NCHUNK)                     // 4689 -> 1.93 rounds, 96% util
#define TPB      512
#define WPC      (TPB / 32)
#define REG_C    0.001
// X tile: [row][col], row stride 12 words (48 B = 3 x 16B units; 3 coprime 8 ->
// LDS.128 conflict-free across lanes reading consecutive rows)
#define XSTRIDE  12
#define XTILE_W  (ROWBLK * XSTRIDE)
#define SMEM_W   (D_PAD * C_CLS)
#define SMEM_BYTES ((SMEM_W + WPC * XTILE_W) * 4)   // 161280+49152 = 210432 B

__device__ float  g_parts[NCHUNK][N_ROWS][C_CLS];  // 24MB partials, each slot written once
__device__ double g_loss;
__device__ double g_sqsum;
__device__ int    g_y_is_i64;

// ---- packed f32x2 helpers (ptxas never emits FFMA2 from C++) ----
__device__ __forceinline__ unsigned long long pack2(float v) {
    unsigned long long r;
    asm("mov.b64 %0, {%1,%1};" : "=l"(r) : "f"(v));
    return r;
}
__device__ __forceinline__ void unpack2(unsigned long long v, float& lo, float& hi) {
    asm("mov.b64 {%0,%1}, %2;" : "=f"(lo), "=f"(hi) : "l"(v));
}
__device__ __forceinline__ void ffma2(unsigned long long& acc, unsigned long long a,
                                      unsigned long long b) {
    asm("fma.rn.f32x2 %0, %1, %2, %0;" : "+l"(acc) : "l"(a), "l"(b));
}

__global__ void init_kernel() {
    g_loss  = 0.0;
    g_sqsum = 0.0;
}

__global__ void sqsum_kernel(const float* __restrict__ iw, int n) {
    float s = 0.0f;
    for (int i = blockIdx.x * blockDim.x + threadIdx.x; i < n; i += gridDim.x * blockDim.x) {
        float v = iw[i];
        s = fmaf(v, v, s);
    }
    #pragma unroll
    for (int o = 16; o > 0; o >>= 1) s += __shfl_xor_sync(0xffffffffu, s, o);
    if ((threadIdx.x & 31) == 0) atomicAdd(&g_sqsum, (double)s);
}

// Y dtype probe (int64 LE -> int32 view zero at odd idx; 128 zeros impossible
// for genuine int32 labels from [0,20)).
__global__ void probe_kernel(const int* __restrict__ y32) {
    int nz = 0;
    for (int i = threadIdx.x; i < 128; i += 32)
        if (y32[2 * i + 1] != 0) nz = 1;
    unsigned any = __ballot_sync(0xffffffffu, nz);
    if (threadIdx.x == 0) g_y_is_i64 = (any == 0u);
}

// GEMM partials: 2 rows per lane (warp = 64 rows), W broadcast from smem.
// Each w2 LDS.128 feeds 4 FFMA2 (R6 profile: L1tex 67.6% binding at 1 row/lane).
__global__ void __launch_bounds__(TPB, 1)
gemm_kernel(const float* __restrict__ W, const float* __restrict__ X) {
    extern __shared__ float sm[];
    float* wsm = sm;                                  // [j*20 + c], j < D_PAD
    const int lane = threadIdx.x & 31;
    const int warp = threadIdx.x >> 5;
    float* tile = sm + SMEM_W + warp * XTILE_W;       // [row*12 + col], 64 rows

    // Fill W [c][j] -> wsm[j*20+c], zero-padded to D_PAD.
    for (int idx = threadIdx.x; idx < C_CLS * D_PAD; idx += TPB) {
        int c = idx / D_PAD;
        int j = idx - c * D_PAD;
        wsm[j * C_CLS + c] = (j < D_DIM) ? W[c * D_DIM + j] : 0.0f;
    }
    __syncthreads();

    const int gw     = blockIdx.x * WPC + warp;
    const int nwarps = gridDim.x * WPC;
    const int lr     = lane >> 3;        // staging: row offset 0..3
    const int lc     = lane & 7;         // staging: col 0..7

    for (int t = gw; t < NTASK; t += nwarps) {
        const int rb = t / NCHUNK;
        const int ch = t - rb * NCHUNK;
        const int r0 = rb * ROWBLK;
        const int c0 = ch * CHUNK;

        unsigned long long acc[2][10];
        #pragma unroll
        for (int r = 0; r < 2; r++)
            #pragma unroll
            for (int k = 0; k < 10; k++) acc[r][k] = 0ull;

        // stage tile 0: LDG k covers rows (4k..4k+3) x cols 0..7, coalesced 32B
        float st[16];
        {
            const bool fast = (c0 + TILE <= D_DIM);
            #pragma unroll
            for (int k = 0; k < 16; k++) {
                int row = r0 + 4 * k + lr;
                if (row >= N_ROWS) row = N_ROWS - 1;      // clamp (discarded later)
                const int col = c0 + lc;
                st[k] = (fast || col < D_DIM) ? __ldg(X + (size_t)row * D_DIM + col) : 0.0f;
            }
            #pragma unroll
            for (int k = 0; k < 16; k++)
                tile[(4 * k + lr) * XSTRIDE + lc] = st[k];
        }
        __syncwarp();

        for (int tt = 0; tt < NTILES; tt++) {
            // prefetch next tile into regs (overlaps compute)
            if (tt + 1 < NTILES) {
                const int jgn = c0 + (tt + 1) * TILE;
                const bool fast = (jgn + TILE <= D_DIM);
                #pragma unroll
                for (int k = 0; k < 16; k++) {
                    int row = r0 + 4 * k + lr;
                    if (row >= N_ROWS) row = N_ROWS - 1;
                    const int col = jgn + lc;
                    st[k] = (fast || col < D_DIM) ? __ldg(X + (size_t)row * D_DIM + col) : 0.0f;
                }
            }

            // compute: lane owns rows lane and lane+32; uniform j, broadcast W
            const int jg = c0 + tt * TILE;
            #pragma unroll
            for (int j4 = 0; j4 < TILE; j4 += 4) {
                const float4 xv0 = *(const float4*)(tile + lane * XSTRIDE + j4);
                const float4 xv1 = *(const float4*)(tile + (lane + 32) * XSTRIDE + j4);
                const float xs0[4] = {xv0.x, xv0.y, xv0.z, xv0.w};
                const float xs1[4] = {xv1.x, xv1.y, xv1.z, xv1.w};
                #pragma unroll
                for (int u = 0; u < 4; u++) {
                    const unsigned long long xx0 = pack2(xs0[u]);
                    const unsigned long long xx1 = pack2(xs1[u]);
                    const ulonglong2* wr = (const ulonglong2*)(wsm + (jg + j4 + u) * C_CLS);
                    #pragma unroll
                    for (int k = 0; k < 5; k++) {
                        const ulonglong2 w2 = wr[k];
                        ffma2(acc[0][2 * k],     xx0, w2.x);
                        ffma2(acc[0][2 * k + 1], xx0, w2.y);
                        ffma2(acc[1][2 * k],     xx1, w2.x);
                        ffma2(acc[1][2 * k + 1], xx1, w2.y);
                    }
                }
            }
            __syncwarp();

            if (tt + 1 < NTILES) {
                #pragma unroll
                for (int k = 0; k < 16; k++)
                    tile[(4 * k + lr) * XSTRIDE + lc] = st[k];
            }
            __syncwarp();
        }

        // write partials: rows r0+lane and r0+32+lane (5 x STG.128 each)
        #pragma unroll
        for (int r = 0; r < 2; r++) {
            const int row = r0 + 32 * r + lane;
            if (row < N_ROWS) {
                float s[20];
                #pragma unroll
                for (int k = 0; k < 10; k++) unpack2(acc[r][k], s[2 * k], s[2 * k + 1]);
                float4* dst = (float4*)&g_parts[ch][row][0];
                #pragma unroll
                for (int k = 0; k < 5; k++)
                    dst[k] = make_float4(s[4 * k], s[4 * k + 1], s[4 * k + 2], s[4 * k + 3]);
            }
        }
    }
}

// Per-row: sum 3 partials, picked + logsumexp(-scores), reduce into g_loss.
__global__ void lse_kernel(const int* __restrict__ Y) {
    const int row = blockIdx.x * blockDim.x + threadIdx.x;
    float myloss = 0.0f;
    if (row < N_ROWS) {
        float s[C_CLS];
        const float4* p0 = (const float4*)&g_parts[0][row][0];
        const float4* p1 = (const float4*)&g_parts[1][row][0];
        const float4* p2 = (const float4*)&g_parts[2][row][0];
        #pragma unroll
        for (int k = 0; k < 5; k++) {
            float4 a = p0[k], b = p1[k], c = p2[k];
            s[4 * k]     = a.x + b.x + c.x;
            s[4 * k + 1] = a.y + b.y + c.y;
            s[4 * k + 2] = a.z + b.z + c.z;
            s[4 * k + 3] = a.w + b.w + c.w;
        }
        const int y = Y[row * (g_y_is_i64 ? 2 : 1)];
        float picked = 0.0f;
        float m = -s[0];
        #pragma unroll
        for (int c = 0; c < C_CLS; c++) {
            if (c == y) picked = s[c];
            m = fmaxf(m, -s[c]);
        }
        float sum = 0.0f;
        #pragma unroll
        for (int c = 0; c < C_CLS; c++) sum += __expf(-s[c] - m);
        myloss = picked + m + __logf(sum);
    }
    #pragma unroll
    for (int o = 16; o > 0; o >>= 1) myloss += __shfl_xor_sync(0xffffffffu, myloss, o);
    if ((threadIdx.x & 31) == 0) atomicAdd(&g_loss, (double)myloss);
}

__global__ void fin_kernel(float* out) {
    out[0] = (float)(g_loss / (double)N_ROWS + REG_C * sqrt(g_sqsum));
}

extern "C" void kernel_launch(void* const* d_in, const int* in_sizes, int n_in,
                              void* d_out, int out_size) {
    const float* W  = (const float*)d_in[0];  // weights [C, D]
    const float* X  = (const float*)d_in[1];  // X [N, D]
    const int*   Y  = (const int*)d_in[2];    // Y [N] (int32 or int64, probed)
    const float* IW = (const float*)d_in[3];  // init_weights [C, D]
    float* out = (float*)d_out;

    int sms = 148;
    cudaDeviceGetAttribute(&sms, cudaDevAttrMultiProcessorCount, 0);

    cudaFuncSetAttribute(gemm_kernel, cudaFuncAttributeMaxDynamicSharedMemorySize,
                         SMEM_BYTES);

    // graph-kernel index 3 = gemm_kernel (the ncu-captured slot)
    init_kernel<<<1, 1>>>();
    sqsum_kernel<<<64, 256>>>(IW, C_CLS * D_DIM);
    probe_kernel<<<1, 32>>>(Y);
    gemm_kernel<<<sms, TPB, SMEM_BYTES>>>(W, X);
    lse_kernel<<<(N_ROWS + 255) / 256, 256>>>(Y);
    fin_kernel<<<1, 1>>>(out);
}

// round 10
// speedup vs baseline: 2.7045x; 2.7045x over previous
#include <cuda_runtime.h>
#include <cuda_bf16.h>
#include <cstdint>
#include <math.h>

#define N_ROWS   100000
#define C_CLS    20
#define D_DIM    2001
#define REG_C    0.001
#define MTILE    128
#define KSTAGE   32
#define NSTAGE   63            // 63*32 = 2016 >= 2001 (guarded tail)
#define NCTA     ((N_ROWS + MTILE - 1) / MTILE)   // 782
#define TPB      256

// per-stage smem: Ahi[128][64B]=8192 | Alo 8192 | Bhi[24][80B]=1920 | Blo 1920
#define ST_AHI   0
#define ST_ALO   8192
#define ST_BHI   16384
#define ST_BLO   18304
#define STAGE_BYTES 20224
#define SMEM_TOTAL  (2 * STAGE_BYTES)   // 40448 B

__device__ double g_loss;
__device__ double g_sqsum;
__device__ int    g_y_is_i64;

__device__ __forceinline__ uint32_t smem_u32(const void* p) {
    uint32_t a;
    asm("{ .reg .u64 t; cvta.to.shared.u64 t, %1; cvt.u32.u64 %0, t; }" : "=r"(a) : "l"(p));
    return a;
}
// A-tile byte offset with XOR swizzle: row r (0..127) x col k (0..31) bf16.
// 64B rows; 16B unit index = (k>>3) ^ ((r>>1)&3) -> ldmatrix & STS conflict-free.
__device__ __forceinline__ uint32_t a_off(int r, int k) {
    return (uint32_t)(r * 64 + 16 * (((k >> 3) ^ ((r >> 1) & 3))) + (k & 7) * 2);
}
// split two fp32 into packed bf16x2 hi and lo (Dekker split)
__device__ __forceinline__ void split2(float x0, float x1, uint32_t& hp, uint32_t& lp) {
    asm("cvt.rn.bf16x2.f32 %0, %1, %2;" : "=r"(hp) : "f"(x1), "f"(x0));
    float h0 = __uint_as_float(hp << 16);
    float h1 = __uint_as_float(hp & 0xFFFF0000u);
    float r0 = x0 - h0, r1 = x1 - h1;
    asm("cvt.rn.bf16x2.f32 %0, %1, %2;" : "=r"(lp) : "f"(r1), "f"(r0));
}
#define LDSM_X4(r, a) \
    asm volatile("ldmatrix.sync.aligned.m8n8.x4.shared.b16 {%0,%1,%2,%3}, [%4];" \
        : "=r"((r)[0]), "=r"((r)[1]), "=r"((r)[2]), "=r"((r)[3]) : "r"(a))
#define MMA16816(d, a, b0, b1) \
    asm volatile("mma.sync.aligned.m16n8k16.row.col.f32.bf16.bf16.f32 " \
        "{%0,%1,%2,%3}, {%4,%5,%6,%7}, {%8,%9}, {%0,%1,%2,%3};" \
        : "+f"((d)[0]), "+f"((d)[1]), "+f"((d)[2]), "+f"((d)[3]) \
        : "r"((a)[0]), "r"((a)[1]), "r"((a)[2]), "r"((a)[3]), "r"(b0), "r"(b1))

__global__ void init_kernel() { g_loss = 0.0; g_sqsum = 0.0; }

__global__ void sqsum_kernel(const float* __restrict__ iw, int n) {
    float s = 0.0f;
    for (int i = blockIdx.x * blockDim.x + threadIdx.x; i < n; i += gridDim.x * blockDim.x) {
        float v = iw[i];
        s = fmaf(v, v, s);
    }
    #pragma unroll
    for (int o = 16; o > 0; o >>= 1) s += __shfl_xor_sync(0xffffffffu, s, o);
    if ((threadIdx.x & 31) == 0) atomicAdd(&g_sqsum, (double)s);
}

// Y dtype probe: int64 LE -> int32 view zero at all odd indices.
__global__ void probe_kernel(const int* __restrict__ y32) {
    int nz = 0;
    for (int i = threadIdx.x; i < 128; i += 32)
        if (y32[2 * i + 1] != 0) nz = 1;
    unsigned any = __ballot_sync(0xffffffffu, nz);
    if (threadIdx.x == 0) g_y_is_i64 = (any == 0u);
}

// Fused split-bf16 mma.sync GEMM + logistic loss. CTA = 128 rows x 20 classes.
__global__ void __launch_bounds__(TPB, 4)
gemm_kernel(const float* __restrict__ W, const float* __restrict__ X,
            const int* __restrict__ Y) {
    extern __shared__ char smc[];
    const uint32_t sb = smem_u32(smc);
    const int tid = threadIdx.x, wid = tid >> 5, lid = tid & 31;
    const int r0 = blockIdx.x * MTILE;

    float acc[3][4];
    #pragma unroll
    for (int t = 0; t < 3; t++)
        #pragma unroll
        for (int i = 0; i < 4; i++) acc[t][i] = 0.0f;

    const int frow = tid >> 4;       // 0..15
    const int ft   = tid & 15;       // col-pair index
    float xr[16], br[4];

    // ldmatrix lane geometry (fixed per thread)
    const int q   = lid >> 3;
    const int rr  = 16 * wid + (q & 1) * 8 + (lid & 7);
    const int kqh = (q >> 1) * 8;
    // B-fragment lane geometry
    const int bg  = lid >> 2;        // class-within-ntile (0..7)
    const int bk  = (lid & 3) * 2;   // k offset (0,2,4,6)

    #define LDG_STAGE(s) do { \
        const int k0_ = (s) * KSTAGE; \
        const int c_ = k0_ + 2 * ft; \
        _Pragma("unroll") \
        for (int i = 0; i < 8; i++) { \
            const int gr_ = r0 + 16 * i + frow; \
            const bool rok_ = gr_ < N_ROWS; \
            const float* xp_ = X + (size_t)gr_ * D_DIM; \
            xr[2*i]   = (rok_ && c_     < D_DIM) ? __ldg(xp_ + c_)     : 0.0f; \
            xr[2*i+1] = (rok_ && c_ + 1 < D_DIM) ? __ldg(xp_ + c_ + 1) : 0.0f; \
        } \
        br[0] = (frow < C_CLS && c_     < D_DIM) ? __ldg(W + (size_t)frow * D_DIM + c_)     : 0.0f; \
        br[1] = (frow < C_CLS && c_ + 1 < D_DIM) ? __ldg(W + (size_t)frow * D_DIM + c_ + 1) : 0.0f; \
        const int cls1_ = 16 + frow; \
        const bool a1_ = (tid < 128) && (cls1_ < C_CLS); \
        br[2] = (a1_ && c_     < D_DIM) ? __ldg(W + (size_t)cls1_ * D_DIM + c_)     : 0.0f; \
        br[3] = (a1_ && c_ + 1 < D_DIM) ? __ldg(W + (size_t)cls1_ * D_DIM + c_ + 1) : 0.0f; \
    } while (0)

    #define STS_STAGE(buf) do { \
        char* st_ = smc + (buf) * STAGE_BYTES; \
        _Pragma("unroll") \
        for (int i = 0; i < 8; i++) { \
            uint32_t hp_, lp_; \
            split2(xr[2*i], xr[2*i+1], hp_, lp_); \
            const uint32_t off_ = a_off(16 * i + frow, 2 * ft); \
            *(uint32_t*)(st_ + ST_AHI + off_) = hp_; \
            *(uint32_t*)(st_ + ST_ALO + off_) = lp_; \
        } \
        { uint32_t hp_, lp_; \
          split2(br[0], br[1], hp_, lp_); \
          *(uint32_t*)(st_ + ST_BHI + frow * 80 + 4 * ft) = hp_; \
          *(uint32_t*)(st_ + ST_BLO + frow * 80 + 4 * ft) = lp_; \
          if (tid < 128) { \
              split2(br[2], br[3], hp_, lp_); \
              *(uint32_t*)(st_ + ST_BHI + (16 + frow) * 80 + 4 * ft) = hp_; \
              *(uint32_t*)(st_ + ST_BLO + (16 + frow) * 80 + 4 * ft) = lp_; \
          } } \
    } while (0)

    #define COMPUTE(buf) do { \
        const uint32_t sa_ = sb + (buf) * STAGE_BYTES; \
        const char* bp_ = smc + (buf) * STAGE_BYTES; \
        _Pragma("unroll") \
        for (int ks = 0; ks < 2; ks++) { \
            uint32_t ah_[4], al_[4]; \
            const uint32_t ao_ = a_off(rr, ks * 16 + kqh); \
            LDSM_X4(ah_, sa_ + ST_AHI + ao_); \
            LDSM_X4(al_, sa_ + ST_ALO + ao_); \
            _Pragma("unroll") \
            for (int t = 0; t < 3; t++) { \
                const char* bb_ = bp_ + (t * 8 + bg) * 80 + (ks * 16 + bk) * 2; \
                const uint32_t bh0_ = *(const uint32_t*)(bb_ + ST_BHI); \
                const uint32_t bh1_ = *(const uint32_t*)(bb_ + ST_BHI + 16); \
                const uint32_t bl0_ = *(const uint32_t*)(bb_ + ST_BLO); \
                const uint32_t bl1_ = *(const uint32_t*)(bb_ + ST_BLO + 16); \
                MMA16816(acc[t], ah_, bh0_, bh1_); \
                MMA16816(acc[t], ah_, bl0_, bl1_); \
                MMA16816(acc[t], al_, bh0_, bh1_); \
            } \
        } \
    } while (0)

    LDG_STAGE(0);
    STS_STAGE(0);
    __syncthreads();
    for (int s = 0; s < NSTAGE; s++) {
        if (s + 1 < NSTAGE) LDG_STAGE(s + 1);
        COMPUTE(s & 1);
        if (s + 1 < NSTAGE) STS_STAGE((s + 1) & 1);
        __syncthreads();
    }

    // epilogue: scatter scores to smem [128][25], then per-row loss
    float* sc = (float*)smc;
    {
        const int g = lid >> 2, t2 = (lid & 3) * 2;
        const int row0 = 16 * wid + g;
        #pragma unroll
        for (int t = 0; t < 3; t++) {
            sc[row0 * 25 + t * 8 + t2]           = acc[t][0];
            sc[row0 * 25 + t * 8 + t2 + 1]       = acc[t][1];
            sc[(row0 + 8) * 25 + t * 8 + t2]     = acc[t][2];
            sc[(row0 + 8) * 25 + t * 8 + t2 + 1] = acc[t][3];
        }
    }
    __syncthreads();
    if (tid < 128) {
        const int row = r0 + tid;
        float myloss = 0.0f;
        if (row < N_ROWS) {
            const int y = Y[row * (g_y_is_i64 ? 2 : 1)];
            float s[C_CLS];
            #pragma unroll
            for (int c = 0; c < C_CLS; c++) s[c] = sc[tid * 25 + c];
            float picked = 0.0f, m = -s[0];
            #pragma unroll
            for (int c = 0; c < C_CLS; c++) {
                if (c == y) picked = s[c];
                m = fmaxf(m, -s[c]);
            }
            float sum = 0.0f;
            #pragma unroll
            for (int c = 0; c < C_CLS; c++) sum += __expf(-s[c] - m);
            myloss = picked + m + __logf(sum);
        }
        #pragma unroll
        for (int o = 16; o > 0; o >>= 1)
            myloss += __shfl_xor_sync(0xffffffffu, myloss, o);
        if (lid == 0) atomicAdd(&g_loss, (double)myloss);
    }
}

__global__ void fin_kernel(float* out) {
    out[0] = (float)(g_loss / (double)N_ROWS + REG_C * sqrt(g_sqsum));
}

extern "C" void kernel_launch(void* const* d_in, const int* in_sizes, int n_in,
                              void* d_out, int out_size) {
    const float* W  = (const float*)d_in[0];  // weights [C, D]
    const float* X  = (const float*)d_in[1];  // X [N, D]
    const int*   Y  = (const int*)d_in[2];    // Y [N] (int32 or int64, probed)
    const float* IW = (const float*)d_in[3];  // init_weights [C, D]
    float* out = (float*)d_out;

    cudaFuncSetAttribute(gemm_kernel, cudaFuncAttributeMaxDynamicSharedMemorySize,
                         SMEM_TOTAL);

    // graph-kernel index 3 = gemm_kernel (the ncu-captured slot)
    init_kernel<<<1, 1>>>();
    sqsum_kernel<<<64, 256>>>(IW, C_CLS * D_DIM);
    probe_kernel<<<1, 32>>>(Y);
    gemm_kernel<<<NCTA, TPB, SMEM_TOTAL>>>(W, X, Y);
    fin_kernel<<<1, 1>>>(out);
}

// round 12
// speedup vs baseline: 2.7539x; 1.0183x over previous
#include <cuda_runtime.h>
#include <cuda_bf16.h>
#include <cstdint>
#include <math.h>

#define N_ROWS   100000
#define C_CLS    20
#define D_DIM    2001
#define REG_C    0.001
#define MTILE    128
#define KSTAGE   32
#define NSTAGE   63            // 63*32 = 2016 >= 2001 (zero-filled tail)
#define NCTA     ((N_ROWS + MTILE - 1) / MTILE)   // 782
#define TPB      256

// per-stage smem: A fp32 [128 rows][40 words] (160B stride, LDS.64 conflict-free)
// then Bhi/Blo bf16 [24][80B]
#define ST_A     0
#define ST_BHI   20480
#define ST_BLO   22400
#define STAGE_BYTES 24320
#define SMEM_TOTAL  (2 * STAGE_BYTES)   // 48640 B -> 4 CTAs/SM

__device__ double g_loss;
__device__ double g_sqsum;
__device__ int    g_y_is_i64;

__device__ __forceinline__ uint32_t smem_u32(const void* p) {
    uint32_t a;
    asm("{ .reg .u64 t; cvta.to.shared.u64 t, %1; cvt.u32.u64 %0, t; }" : "=r"(a) : "l"(p));
    return a;
}
// split two fp32 into packed bf16x2 hi and lo (Dekker split)
__device__ __forceinline__ void split2(float x0, float x1, uint32_t& hp, uint32_t& lp) {
    asm("cvt.rn.bf16x2.f32 %0, %1, %2;" : "=r"(hp) : "f"(x1), "f"(x0));
    float h0 = __uint_as_float(hp << 16);
    float h1 = __uint_as_float(hp & 0xFFFF0000u);
    float r0 = x0 - h0, r1 = x1 - h1;
    asm("cvt.rn.bf16x2.f32 %0, %1, %2;" : "=r"(lp) : "f"(r1), "f"(r0));
}
#define CP_A4(dst, src, sz) \
    asm volatile("cp.async.ca.shared.global [%0], [%1], 4, %2;" \
        :: "r"(dst), "l"(src), "r"(sz) : "memory")
#define CP_COMMIT() asm volatile("cp.async.commit_group;" ::: "memory")
#define CP_WAIT0()  asm volatile("cp.async.wait_group 0;" ::: "memory")
#define MMA16816(d, a, b0, b1) \
    asm volatile("mma.sync.aligned.m16n8k16.row.col.f32.bf16.bf16.f32 " \
        "{%0,%1,%2,%3}, {%4,%5,%6,%7}, {%8,%9}, {%0,%1,%2,%3};" \
        : "+f"((d)[0]), "+f"((d)[1]), "+f"((d)[2]), "+f"((d)[3]) \
        : "r"((a)[0]), "r"((a)[1]), "r"((a)[2]), "r"((a)[3]), "r"(b0), "r"(b1))

__global__ void init_kernel() { g_loss = 0.0; g_sqsum = 0.0; }

__global__ void sqsum_kernel(const float* __restrict__ iw, int n) {
    float s = 0.0f;
    for (int i = blockIdx.x * blockDim.x + threadIdx.x; i < n; i += gridDim.x * blockDim.x) {
        float v = iw[i];
        s = fmaf(v, v, s);
    }
    #pragma unroll
    for (int o = 16; o > 0; o >>= 1) s += __shfl_xor_sync(0xffffffffu, s, o);
    if ((threadIdx.x & 31) == 0) atomicAdd(&g_sqsum, (double)s);
}

// Y dtype probe: int64 LE -> int32 view zero at all odd indices.
__global__ void probe_kernel(const int* __restrict__ y32) {
    int nz = 0;
    for (int i = threadIdx.x; i < 128; i += 32)
        if (y32[2 * i + 1] != 0) nz = 1;
    unsigned any = __ballot_sync(0xffffffffu, nz);
    if (threadIdx.x == 0) g_y_is_i64 = (any == 0u);
}

// Fused split-bf16 mma.sync GEMM + logistic loss, cp.async fp32 staging.
__global__ void __launch_bounds__(TPB, 4)
gemm_kernel(const float* __restrict__ W, const float* __restrict__ X,
            const int* __restrict__ Y) {
    extern __shared__ char smc[];
    const uint32_t sb = smem_u32(smc);
    const int tid = threadIdx.x, wid = tid >> 5, lid = tid & 31;
    const int r0 = blockIdx.x * MTILE;
    const bool ctafull = (r0 + MTILE <= N_ROWS);

    const int g  = lid >> 2;         // fragment row-in-8
    const int t4 = lid & 3;          // fragment col-quad
    const uint32_t aoff0 = (uint32_t)((16 * wid + g) * 160 + t4 * 8);

    float acc[3][4];
    #pragma unroll
    for (int t = 0; t < 3; t++)
        #pragma unroll
        for (int i = 0; i < 4; i++) acc[t][i] = 0.0f;

    // ---- A staging: 16 cp.async.4B per thread, rows wid+8i, col = lane ----
    #define ISSUE_A(s) do { \
        const int c0_ = (s) * KSTAGE; \
        const uint32_t colsz_ = (c0_ + lid < D_DIM) ? 4u : 0u; \
        const uint32_t db_ = sb + ((s) & 1) * STAGE_BYTES + ST_A + (uint32_t)(wid * 160 + lid * 4); \
        const float* sp_ = X + (size_t)(r0 + wid) * D_DIM + c0_ + lid; \
        if (ctafull) { \
            _Pragma("unroll") \
            for (int i = 0; i < 16; i++) \
                CP_A4(db_ + (uint32_t)(i * 8 * 160), sp_ + (size_t)(8 * i) * D_DIM, colsz_); \
        } else { \
            _Pragma("unroll") \
            for (int i = 0; i < 16; i++) { \
                const uint32_t sz_ = (r0 + wid + 8 * i < N_ROWS) ? colsz_ : 0u; \
                CP_A4(db_ + (uint32_t)(i * 8 * 160), sp_ + (size_t)(8 * i) * D_DIM, sz_); \
            } \
        } \
    } while (0)

    // ---- B staging: 3 elems/thread, split + shfl-pair, STS.32 hi/lo planes ----
    #define LDG_B(s, v) do { \
        const int c0_ = (s) * KSTAGE; \
        _Pragma("unroll") \
        for (int k = 0; k < 3; k++) { \
            const int e_ = tid + 256 * k, row_ = e_ >> 5, col_ = e_ & 31; \
            (v)[k] = (row_ < C_CLS && c0_ + col_ < D_DIM) \
                   ? __ldg(W + (size_t)row_ * D_DIM + c0_ + col_) : 0.0f; \
        } \
    } while (0)

    #define STS_B(s, v) do { \
        char* st_ = smc + ((s) & 1) * STAGE_BYTES; \
        _Pragma("unroll") \
        for (int k = 0; k < 3; k++) { \
            const int e_ = tid + 256 * k, row_ = e_ >> 5, col_ = e_ & 31; \
            const float vv_ = (v)[k]; \
            uint32_t hb_; \
            asm("cvt.rn.bf16x2.f32 %0, %1, %1;" : "=r"(hb_) : "f"(vv_)); \
            hb_ &= 0xFFFFu; \
            const float lo_ = vv_ - __uint_as_float(hb_ << 16); \
            uint32_t lb_; \
            asm("cvt.rn.bf16x2.f32 %0, %1, %1;" : "=r"(lb_) : "f"(lo_)); \
            lb_ &= 0xFFFFu; \
            const uint32_t send_ = (lid & 1) ? hb_ : lb_; \
            const uint32_t recv_ = __shfl_xor_sync(0xffffffffu, send_, 1); \
            const uint32_t boff_ = (uint32_t)(row_ * 80 + (col_ & ~1) * 2); \
            if (lid & 1) *(uint32_t*)(st_ + ST_BLO + boff_) = recv_ | (lb_ << 16); \
            else         *(uint32_t*)(st_ + ST_BHI + boff_) = hb_ | (recv_ << 16); \
        } \
    } while (0)

    #define COMPUTE(buf) do { \
        const char* bp_ = smc + (buf) * STAGE_BYTES; \
        _Pragma("unroll") \
        for (int ks = 0; ks < 2; ks++) { \
            const char* ap_ = bp_ + ST_A + aoff0 + ks * 64; \
            const float2 a0_ = *(const float2*)(ap_); \
            const float2 a1_ = *(const float2*)(ap_ + 1280); \
            const float2 a2_ = *(const float2*)(ap_ + 32); \
            const float2 a3_ = *(const float2*)(ap_ + 1312); \
            uint32_t ah_[4], al_[4]; \
            split2(a0_.x, a0_.y, ah_[0], al_[0]); \
            split2(a1_.x, a1_.y, ah_[1], al_[1]); \
            split2(a2_.x, a2_.y, ah_[2], al_[2]); \
            split2(a3_.x, a3_.y, ah_[3], al_[3]); \
            _Pragma("unroll") \
            for (int t = 0; t < 3; t++) { \
                const char* bb_ = bp_ + (t * 8 + g) * 80 + (ks * 16 + t4 * 2) * 2; \
                const uint32_t bh0_ = *(const uint32_t*)(bb_ + ST_BHI); \
                const uint32_t bh1_ = *(const uint32_t*)(bb_ + ST_BHI + 16); \
                const uint32_t bl0_ = *(const uint32_t*)(bb_ + ST_BLO); \
                const uint32_t bl1_ = *(const uint32_t*)(bb_ + ST_BLO + 16); \
                MMA16816(acc[t], ah_, bh0_, bh1_); \
                MMA16816(acc[t], ah_, bl0_, bl1_); \
                MMA16816(acc[t], al_, bh0_, bh1_); \
            } \
        } \
    } while (0)

    // prologue: stage 0
    float vb[3];
    LDG_B(0, vb);
    STS_B(0, vb);
    ISSUE_A(0);
    CP_COMMIT();

    for (int s = 0; s < NSTAGE; s++) {
        if (s + 1 < NSTAGE) LDG_B(s + 1, vb);   // LDG early, hide behind wait
        CP_WAIT0();
        __syncthreads();          // stage s visible; buffer (s+1)&1 free
        if (s + 1 < NSTAGE) {
            ISSUE_A(s + 1);
            STS_B(s + 1, vb);
            CP_COMMIT();
        }
        COMPUTE(s & 1);
    }

    // epilogue: scatter scores to smem [128][25], then per-row loss
    __syncthreads();
    float* sc = (float*)smc;
    {
        const int row0 = 16 * wid + g;
        #pragma unroll
        for (int t = 0; t < 3; t++) {
            sc[row0 * 25 + t * 8 + t4 * 2]           = acc[t][0];
            sc[row0 * 25 + t * 8 + t4 * 2 + 1]       = acc[t][1];
            sc[(row0 + 8) * 25 + t * 8 + t4 * 2]     = acc[t][2];
            sc[(row0 + 8) * 25 + t * 8 + t4 * 2 + 1] = acc[t][3];
        }
    }
    __syncthreads();
    if (tid < 128) {
        const int row = r0 + tid;
        float myloss = 0.0f;
        if (row < N_ROWS) {
            const int y = Y[row * (g_y_is_i64 ? 2 : 1)];
            float s[C_CLS];
            #pragma unroll
            for (int c = 0; c < C_CLS; c++) s[c] = sc[tid * 25 + c];
            float picked = 0.0f, m = -s[0];
            #pragma unroll
            for (int c = 0; c < C_CLS; c++) {
                if (c == y) picked = s[c];
                m = fmaxf(m, -s[c]);
            }
            float sum = 0.0f;
            #pragma unroll
            for (int c = 0; c < C_CLS; c++) sum += __expf(-s[c] - m);
            myloss = picked + m + __logf(sum);
        }
        #pragma unroll
        for (int o = 16; o > 0; o >>= 1)
            myloss += __shfl_xor_sync(0xffffffffu, myloss, o);
        if (lid == 0) atomicAdd(&g_loss, (double)myloss);
    }
}

__global__ void fin_kernel(float* out) {
    out[0] = (float)(g_loss / (double)N_ROWS + REG_C * sqrt(g_sqsum));
}

extern "C" void kernel_launch(void* const* d_in, const int* in_sizes, int n_in,
                              void* d_out, int out_size) {
    const float* W  = (const float*)d_in[0];  // weights [C, D]
    const float* X  = (const float*)d_in[1];  // X [N, D]
    const int*   Y  = (const int*)d_in[2];    // Y [N] (int32 or int64, probed)
    const float* IW = (const float*)d_in[3];  // init_weights [C, D]
    float* out = (float*)d_out;

    cudaFuncSetAttribute(gemm_kernel, cudaFuncAttributeMaxDynamicSharedMemorySize,
                         SMEM_TOTAL);

    // graph-kernel index 3 = gemm_kernel (the ncu-captured slot)
    init_kernel<<<1, 1>>>();
    sqsum_kernel<<<64, 256>>>(IW, C_CLS * D_DIM);
    probe_kernel<<<1, 32>>>(Y);
    gemm_kernel<<<NCTA, TPB, SMEM_TOTAL>>>(W, X, Y);
    fin_kernel<<<1, 1>>>(out);
}